// round 7
// baseline (speedup 1.0000x reference)
#include <cuda_runtime.h>

#define NN 131072
#define DD 64
#define KK 512
#define ITERS 5
#define NT 32            // centers per smem tile
#define NTILES (KK / NT)
#define RB 64            // rows per block
#define MR 4             // rows per thread
#define NC 4             // centers per thread

#define FP_SCALE 1099511627776.0f          // 2^40 (exact exponent shift)
#define FP_INV   (1.0 / 1099511627776.0)   // 2^-40 (double)

// ---------------- scratch (device globals; no allocation allowed) ----------
__device__ __align__(256) float g_centers[KK * DD];
__device__ float g_c2[KK];
__device__ __align__(256) unsigned long long g_isums[KK * DD];  // fixed-point sums
__device__ int   g_icounts[KK];
__device__ int   g_assign[NN];

// ---------------- packed f32x2 + smem helpers -------------------------------
__device__ __forceinline__ unsigned long long fma2(unsigned long long a,
                                                   unsigned long long b,
                                                   unsigned long long c) {
    unsigned long long d;
    asm("fma.rn.f32x2 %0, %1, %2, %3;" : "=l"(d) : "l"(a), "l"(b), "l"(c));
    return d;
}
__device__ __forceinline__ float lo32(unsigned long long v) {
    return __uint_as_float((unsigned)v);
}
__device__ __forceinline__ float hi32(unsigned long long v) {
    return __uint_as_float((unsigned)(v >> 32));
}
__device__ __forceinline__ unsigned long long lds64(unsigned a) {
    unsigned long long v;
    asm("ld.shared.b64 %0, [%1];" : "=l"(v) : "r"(a));
    return v;
}
__device__ __forceinline__ float4 lds128(unsigned a) {
    float4 v;
    asm("ld.shared.v4.f32 {%0,%1,%2,%3}, [%4];"
        : "=f"(v.x), "=f"(v.y), "=f"(v.z), "=f"(v.w) : "r"(a));
    return v;
}
__device__ __forceinline__ void cp_async16(unsigned s, const void* g) {
    asm volatile("cp.async.cg.shared.global [%0], [%1], 16;\n" :: "r"(s), "l"(g));
}
__device__ __forceinline__ void cp_commit() {
    asm volatile("cp.async.commit_group;\n");
}
__device__ __forceinline__ void cp_wait2() {
    asm volatile("cp.async.wait_group 2;\n");
}
__device__ __forceinline__ void cp_wait1() {
    asm volatile("cp.async.wait_group 1;\n");
}
__device__ __forceinline__ void cp_wait0() {
    asm volatile("cp.async.wait_group 0;\n");
}
// no-return 64-bit add (REDG.ADD.64); wraparound gives signed semantics
__device__ __forceinline__ void red_add_u64(unsigned long long* p, unsigned long long v) {
    asm volatile("red.global.add.u64 [%0], %1;\n" :: "l"(p), "l"(v) : "memory");
}

// ---------------- prep: zero sums/counts, c2 of initial centers ------------
__global__ void prep_kernel(const float* __restrict__ centers0) {
    int k = blockIdx.x;
    int d = threadIdx.x;
    float v = centers0[k * DD + d];
    g_isums[k * DD + d] = 0ULL;
    if (d == 0) g_icounts[k] = 0;

    float s = __fmul_rn(v, v);
    #pragma unroll
    for (int o = 16; o > 0; o >>= 1) s += __shfl_down_sync(0xffffffffu, s, o);
    __shared__ float sh[2];
    if ((d & 31) == 0) sh[d >> 5] = s;
    __syncthreads();
    if (d == 0) g_c2[k] = __fadd_rn(sh[0], sh[1]);
}

// ---------------- assign + accumulate (register-blocked GEMM) ---------------
// 128 threads = 16 row-groups (ty) x 8 center-groups (tx). Thread computes a
// 4x4 (row x center) accumulator tile. X block tile (64x64) resident in smem;
// center tiles (32x64) cp.async double-buffered. Smem chunk-XOR swizzle.
// Per-(row,center) summation order bit-identical to validated rounds 1-4.
// Cluster sums accumulated in 2^40 fixed-point int64 -> order-independent,
// fully deterministic across replays.
__global__ __launch_bounds__(128, 4) void assign_kernel(
    const float* __restrict__ X,
    const float* __restrict__ centers0,
    int iter)
{
    const float* __restrict__ C = (iter == 0) ? centers0 : g_centers;

    __shared__ __align__(16) float xs[RB * DD];        // 16 KB
    __shared__ __align__(16) float cs[2][NT * DD];     // 2 x 8 KB
    __shared__ float sc2[KK];
    __shared__ int   sbidx[RB];

    const int tid = threadIdx.x;
    const int tx  = tid & 7;     // center group
    const int ty  = tid >> 3;    // row group
    const int swx = ty & 7;
    const int swc = tx & 7;

    const unsigned xs_b  = (unsigned)__cvta_generic_to_shared(xs);
    const unsigned cs_b0 = (unsigned)__cvta_generic_to_shared(&cs[0][0]);
    const unsigned cs_b1 = (unsigned)__cvta_generic_to_shared(&cs[1][0]);

    // stage all c2 (consumed after first in-loop barrier)
    #pragma unroll
    for (int i = 0; i < KK / 128; i++) sc2[tid + i * 128] = g_c2[tid + i * 128];

    // ---- stage X block tile (1024 x 16B chunks, 8 per thread), swizzled ----
    {
        const char* Xg = (const char*)(X + (size_t)blockIdx.x * RB * DD);
        #pragma unroll
        for (int k = 0; k < 8; k++) {
            int id  = tid + k * 128;
            int row = id >> 4, ch = id & 15;
            unsigned dst = xs_b + row * 256 + ((ch ^ ((row >> 2) & 7)) << 4);
            cp_async16(dst, Xg + row * 256 + ch * 16);
        }
        cp_commit();
    }
    // ---- stage center tiles 0,1 ----
    #pragma unroll
    for (int t0 = 0; t0 < 2; t0++) {
        const char* src = (const char*)(C + (size_t)t0 * NT * DD);
        unsigned cb = t0 ? cs_b1 : cs_b0;
        #pragma unroll
        for (int k = 0; k < 4; k++) {
            int id = tid + k * 128;
            int c = id >> 4, ch = id & 15;
            unsigned dst = cb + c * 256 + ((ch ^ ((c >> 2) & 7)) << 4);
            cp_async16(dst, src + c * 256 + ch * 16);
        }
        cp_commit();
    }

    cp_wait2();          // X arrived (tiles 0/1 may still be in flight)
    __syncthreads();

    // ---- x^2 per owned row (identical accumulation order to round 1) ----
    float x2v[MR];
    #pragma unroll
    for (int r = 0; r < MR; r++) {
        unsigned bxr = xs_b + (ty * MR + r) * 256;
        unsigned long long a0 = 0ULL, b0 = 0ULL;
        #pragma unroll
        for (int m = 0; m < 16; m++) {
            unsigned o = ((m ^ swx) << 4);
            unsigned long long p0 = lds64(bxr + o);       // d-pair 2m   (even)
            unsigned long long p1 = lds64(bxr + o + 8);   // d-pair 2m+1 (odd)
            a0 = fma2(p0, p0, a0);
            b0 = fma2(p1, p1, b0);
        }
        x2v[r] = __fadd_rn(__fadd_rn(lo32(a0), hi32(a0)),
                           __fadd_rn(lo32(b0), hi32(b0)));
    }

    float best[MR];
    int   bidx[MR];
    #pragma unroll
    for (int r = 0; r < MR; r++) { best[r] = 3.4e38f; bidx[r] = 0; }

    unsigned bx[MR];
    #pragma unroll
    for (int r = 0; r < MR; r++) bx[r] = xs_b + (ty * MR + r) * 256;

    for (int t = 0; t < NTILES; t++) {
        if (t == NTILES - 1) cp_wait0(); else cp_wait1();
        __syncthreads();
        const unsigned cb = (t & 1) ? cs_b1 : cs_b0;

        unsigned bcn[NC];
        #pragma unroll
        for (int i = 0; i < NC; i++) bcn[i] = cb + (tx * NC + i) * 256;

        unsigned long long A[MR][NC], B[MR][NC];
        #pragma unroll
        for (int r = 0; r < MR; r++)
            #pragma unroll
            for (int i = 0; i < NC; i++) { A[r][i] = 0ULL; B[r][i] = 0ULL; }

        #pragma unroll 2
        for (int m = 0; m < 16; m++) {
            unsigned ox = ((m ^ swx) << 4);
            unsigned oc = ((m ^ swc) << 4);
            unsigned long long xp0[MR], xp1[MR], cp0[NC], cp1[NC];
            #pragma unroll
            for (int r = 0; r < MR; r++) {
                xp0[r] = lds64(bx[r] + ox);
                xp1[r] = lds64(bx[r] + ox + 8);
            }
            #pragma unroll
            for (int i = 0; i < NC; i++) {
                cp0[i] = lds64(bcn[i] + oc);
                cp1[i] = lds64(bcn[i] + oc + 8);
            }
            #pragma unroll
            for (int r = 0; r < MR; r++)
                #pragma unroll
                for (int i = 0; i < NC; i++) {
                    A[r][i] = fma2(xp0[r], cp0[i], A[r][i]);  // even d-pairs
                    B[r][i] = fma2(xp1[r], cp1[i], B[r][i]);  // odd d-pairs
                }
        }

        // fold + argmin update (same fold/d2 ops as validated kernels)
        #pragma unroll
        for (int i = 0; i < NC; i++) {
            int kg = t * NT + tx * NC + i;
            float cc = sc2[kg];
            #pragma unroll
            for (int r = 0; r < MR; r++) {
                float dot = __fadd_rn(__fadd_rn(lo32(A[r][i]), hi32(A[r][i])),
                                      __fadd_rn(lo32(B[r][i]), hi32(B[r][i])));
                float d2 = __fsub_rn(__fadd_rn(x2v[r], cc), __fmul_rn(2.0f, dot));
                if (d2 < best[r]) { best[r] = d2; bidx[r] = kg; }
            }
        }
        __syncthreads();

        if (t + 2 < NTILES) {
            const char* src = (const char*)(C + (size_t)(t + 2) * NT * DD);
            const unsigned db = (t & 1) ? cs_b1 : cs_b0;
            #pragma unroll
            for (int k = 0; k < 4; k++) {
                int id = tid + k * 128;
                int c = id >> 4, ch = id & 15;
                unsigned dst = db + c * 256 + ((ch ^ ((c >> 2) & 7)) << 4);
                cp_async16(dst, src + c * 256 + ch * 16);
            }
            cp_commit();
        }
    }

    // ---- per-row argmin across the 8 tx lanes (first-min tie-break) ----
    #pragma unroll
    for (int r = 0; r < MR; r++) {
        float b = best[r]; int bi = bidx[r];
        #pragma unroll
        for (int off = 4; off > 0; off >>= 1) {
            float ob = __shfl_down_sync(0xffffffffu, b, off, 8);
            int   oi = __shfl_down_sync(0xffffffffu, bi, off, 8);
            if (ob < b || (ob == b && oi < bi)) { b = ob; bi = oi; }
        }
        if (tx == 0) sbidx[ty * MR + r] = bi;
    }
    __syncthreads();

    // ---- epilogue: 2 threads per row; fixed-point int64 reductions ----
    {
        int row  = tid >> 1;       // 0..63
        int half = tid & 1;        // 32 d-values each
        int bi = sbidx[row];
        if (half == 0) {
            g_assign[blockIdx.x * RB + row] = bi;
            atomicAdd(&g_icounts[bi], 1);
        }
        unsigned long long* s = &g_isums[(size_t)bi * DD];
        int sw = (row >> 2) & 7;
        #pragma unroll
        for (int c = 0; c < 8; c++) {
            int ch = half * 8 + c;
            float4 v = lds128(xs_b + row * 256 + ((ch ^ sw) << 4));
            red_add_u64(&s[ch * 4 + 0], (unsigned long long)llrintf(v.x * FP_SCALE));
            red_add_u64(&s[ch * 4 + 1], (unsigned long long)llrintf(v.y * FP_SCALE));
            red_add_u64(&s[ch * 4 + 2], (unsigned long long)llrintf(v.z * FP_SCALE));
            red_add_u64(&s[ch * 4 + 3], (unsigned long long)llrintf(v.w * FP_SCALE));
        }
    }
}

// ---------------- centers update (+ c2, + reset sums/counts) ---------------
__global__ void update_kernel(const float* __restrict__ X,
                              const int* __restrict__ repl,
                              int iter)
{
    int k = blockIdx.x;
    int d = threadIdx.x;
    int   icnt = g_icounts[k];
    long long ll = (long long)g_isums[k * DD + d];
    float s   = (float)((double)ll * FP_INV);
    float cnt = (float)icnt;
    float v   = __fdiv_rn(s, fmaxf(cnt, 1.0f));
    if (v == 0.0f) {
        int r = repl[iter * KK + k];
        v = X[(size_t)r * DD + d];
    }
    g_centers[k * DD + d] = v;
    g_isums[k * DD + d] = 0ULL;
    if (d == 0) g_icounts[k] = 0;

    float sq = __fmul_rn(v, v);
    #pragma unroll
    for (int o = 16; o > 0; o >>= 1) sq += __shfl_down_sync(0xffffffffu, sq, o);
    __shared__ float sh[2];
    if ((d & 31) == 0) sh[d >> 5] = sq;
    __syncthreads();
    if (d == 0) g_c2[k] = __fadd_rn(sh[0], sh[1]);
}

// ---------------- output: [assignments as float | centers] -----------------
__global__ void out_kernel(float* __restrict__ out) {
    int i = blockIdx.x * blockDim.x + threadIdx.x;
    if (i < NN) {
        out[i] = (float)g_assign[i];
    } else if (i < NN + KK * DD) {
        out[i] = g_centers[i - NN];
    }
}

// ---------------- launch ----------------------------------------------------
extern "C" void kernel_launch(void* const* d_in, const int* in_sizes, int n_in,
                              void* d_out, int out_size)
{
    const float* X    = nullptr;
    const float* C0   = nullptr;
    const int*   repl = nullptr;
    for (int i = 0; i < n_in; i++) {
        if (in_sizes[i] == NN * DD)       X    = (const float*)d_in[i];
        else if (in_sizes[i] == KK * DD)  C0   = (const float*)d_in[i];
        else if (in_sizes[i] == ITERS*KK) repl = (const int*)d_in[i];
    }
    float* out = (float*)d_out;

    // same work every call (no guards): request max smem carveout
    cudaFuncSetAttribute(assign_kernel,
                         cudaFuncAttributePreferredSharedMemoryCarveout,
                         cudaSharedmemCarveoutMaxShared);

    prep_kernel<<<KK, DD>>>(C0);
    for (int i = 0; i < ITERS; i++) {
        assign_kernel<<<NN / RB, 128>>>(X, C0, i);
        update_kernel<<<KK, DD>>>(X, repl, i);
    }
    int total = NN + KK * DD;
    out_kernel<<<(total + 255) / 256, 256>>>(out);
}